// round 12
// baseline (speedup 1.0000x reference)
#include <cuda_runtime.h>

#define FFT_N 1024
#define PADI(i) ((i) + ((i) >> 5))
#define SLEN (FFT_N + (FFT_N >> 5))   // 1056 floats

__device__ __forceinline__ void cmul(float &ar, float &ai, float br, float bi) {
    float r = ar * br - ai * bi;
    float i = ar * bi + ai * br;
    ar = r; ai = i;
}

// forward 4-point DFT in place
__device__ __forceinline__ void dft4(float &r0, float &i0, float &r1, float &i1,
                                     float &r2, float &i2, float &r3, float &i3) {
    float t0r = r0 + r2, t0i = i0 + i2;
    float t1r = r0 - r2, t1i = i0 - i2;
    float t2r = r1 + r3, t2i = i1 + i3;
    float t3r = r1 - r3, t3i = i1 - i3;
    r0 = t0r + t2r; i0 = t0i + t2i;
    r2 = t0r - t2r; i2 = t0i - t2i;
    r1 = t1r + t3i; i1 = t1i - t3r;   // t1 + (-i)*t3
    r3 = t1r - t3i; i3 = t1i + t3r;   // t1 + ( i)*t3
}

// forward 16-point DFT in place; X[r] lands at slot perm(r) = 4*(r&3) + (r>>2)
__device__ __forceinline__ void dft16(float *vr, float *vi) {
    #pragma unroll
    for (int m = 0; m < 4; m++)
        dft4(vr[m], vi[m], vr[m+4], vi[m+4], vr[m+8], vi[m+8], vr[m+12], vi[m+12]);

    const float C1 = 0.92387953251128674f;
    const float S1 = 0.38268343236508978f;
    const float R2 = 0.70710678118654752f;
    cmul(vr[5],  vi[5],   C1, -S1);
    cmul(vr[9],  vi[9],   R2, -R2);
    cmul(vr[13], vi[13],  S1, -C1);
    cmul(vr[6],  vi[6],   R2, -R2);
    { float t = vr[10]; vr[10] = vi[10]; vi[10] = -t; }
    cmul(vr[14], vi[14], -R2, -R2);
    cmul(vr[7],  vi[7],   S1, -C1);
    cmul(vr[11], vi[11], -R2, -R2);
    cmul(vr[15], vi[15], -C1,  S1);

    #pragma unroll
    for (int q = 0; q < 4; q++)
        dft4(vr[4*q], vi[4*q], vr[4*q+1], vi[4*q+1],
             vr[4*q+2], vi[4*q+2], vr[4*q+3], vi[4*q+3]);
}

__global__ __launch_bounds__(64) void dft1024_r16_v2_kernel(
    const float* __restrict__ x,
    const float* __restrict__ dftr,
    const float* __restrict__ dfti,
    float2* __restrict__ out)
{
    __shared__ float  SR[SLEN];
    __shared__ float  SI[SLEN];
    __shared__ float2 STW[256];   // stage-B twiddles, layout [r][jm] (conflict-free broadcast)

    const int u = threadIdx.x;               // 0..63, one FFT per CTA
    const long long pair = blockIdx.x;

    const float* __restrict__ rowA = x + pair * (2 * FFT_N);
    const float* __restrict__ rowB = rowA + FFT_N;
    // Row 1 of the DFT matrix is the exact W_1024 table: (dftr[1024+m], dfti[1024+m])
    const float* __restrict__ twr = dftr + FFT_N;
    const float* __restrict__ twi = dfti + FFT_N;

    // Build stage-B twiddle table: STW[r*16+jm] = W_256^{jm*r} = W_1024^{4*jm*r}
    #pragma unroll
    for (int e = u; e < 256; e += 64) {
        int r  = e >> 4;
        int jm = e & 15;
        int a4 = 4 * jm * r;                 // <= 900 < 1024
        STW[e] = make_float2(twr[a4], twi[a4]);
    }

    float vr[16], vi[16];

    // ── Stage A: radix-16, Ns=1, reads straight from global ──
    #pragma unroll
    for (int r = 0; r < 16; r++) {
        vr[r] = rowA[u + 64 * r];            // z = rowA + i*rowB
        vi[r] = rowB[u + 64 * r];
    }
    dft16(vr, vi);
    #pragma unroll
    for (int r = 0; r < 16; r++) {
        int s = 4 * (r & 3) + (r >> 2);
        SR[PADI(16 * u + r)] = vr[s];
        SI[PADI(16 * u + r)] = vi[s];
    }
    __syncthreads();                         // covers STW build too

    // ── Stage B: radix-16, Ns=16, twiddles from smem table (depth-1) ──
    #pragma unroll
    for (int r = 0; r < 16; r++) {
        vr[r] = SR[PADI(u + 64 * r)];
        vi[r] = SI[PADI(u + 64 * r)];
    }
    {
        const int jm = u & 15;
        #pragma unroll
        for (int r = 1; r < 16; r++) {
            float2 w = STW[r * 16 + jm];
            cmul(vr[r], vi[r], w.x, w.y);
        }
    }
    dft16(vr, vi);
    __syncthreads();
    {
        int base = ((u >> 4) << 8) + (u & 15);
        #pragma unroll
        for (int r = 0; r < 16; r++) {
            int s = 4 * (r & 3) + (r >> 2);
            SR[PADI(base + 16 * r)] = vr[s];
            SI[PADI(base + 16 * r)] = vi[s];
        }
    }
    __syncthreads();

    // ── Stage C: radix-4, Ns=256, per-thread in-place ──
    #pragma unroll
    for (int b = 0; b < 4; b++) {
        int j = u + 64 * b;
        float ar = SR[PADI(j)],        ai = SI[PADI(j)];
        float br = SR[PADI(j + 256)],  bi = SI[PADI(j + 256)];
        float cr = SR[PADI(j + 512)],  ci = SI[PADI(j + 512)];
        float er = SR[PADI(j + 768)],  ei = SI[PADI(j + 768)];

        float w1r = twr[j], w1i = twi[j];
        float w2r = w1r * w1r - w1i * w1i, w2i = 2.0f * w1r * w1i;
        float w3r = w2r * w1r - w2i * w1i, w3i = w2r * w1i + w2i * w1r;
        cmul(br, bi, w1r, w1i);
        cmul(cr, ci, w2r, w2i);
        cmul(er, ei, w3r, w3i);

        float t0r = ar + cr, t0i = ai + ci;
        float t1r = ar - cr, t1i = ai - ci;
        float t2r = br + er, t2i = bi + ei;
        float t3r = br - er, t3i = bi - ei;
        SR[PADI(j)]       = t0r + t2r;  SI[PADI(j)]       = t0i + t2i;
        SR[PADI(j + 512)] = t0r - t2r;  SI[PADI(j + 512)] = t0i - t2i;
        SR[PADI(j + 256)] = t1r + t3i;  SI[PADI(j + 256)] = t1i - t3r;
        SR[PADI(j + 768)] = t1r - t3i;  SI[PADI(j + 768)] = t1i + t3r;
    }
    __syncthreads();

    // ── Pairwise unpack: each smem location read exactly ONCE ──
    float2* __restrict__ outA = out + pair * (2 * FFT_N);
    float2* __restrict__ outB = outA + FFT_N;
    #pragma unroll
    for (int r = 0; r < 8; r++) {
        int k  = u + 64 * r;                 // [0, 512)
        int kn = (FFT_N - k) & (FFT_N - 1);  // mirror (k=0 -> 0, dup-write same value)
        float zr = SR[PADI(k)],  zi = SI[PADI(k)];
        float yr = SR[PADI(kn)], yi = SI[PADI(kn)];
        outA[k]  = make_float2(0.5f * (zr + yr), 0.5f * (zi - yi));
        outB[k]  = make_float2(0.5f * (zi + yi), 0.5f * (yr - zr));
        outA[kn] = make_float2(0.5f * (yr + zr), 0.5f * (yi - zi));
        outB[kn] = make_float2(0.5f * (yi + zi), 0.5f * (zr - yr));
    }
    if (u == 0) {                            // k = 512 self-mirror
        float zr = SR[PADI(512)], zi = SI[PADI(512)];
        outA[512] = make_float2(zr, 0.0f);
        outB[512] = make_float2(zi, 0.0f);
    }
}

extern "C" void kernel_launch(void* const* d_in, const int* in_sizes, int n_in,
                              void* d_out, int out_size)
{
    const float* x    = (const float*)d_in[0];
    const float* dftr = (const float*)d_in[1];
    const float* dfti = (const float*)d_in[2];
    int B = in_sizes[0] / FFT_N;     // 16384 rows
    int pairs = B / 2;               // 8192 complex FFTs, one per 64-thread CTA
    dft1024_r16_v2_kernel<<<pairs, 64>>>(x, dftr, dfti, (float2*)d_out);
}